// round 16
// baseline (speedup 1.0000x reference)
#include <cuda_runtime.h>
#include <cuda_fp16.h>
#include <cstdint>
#include <math.h>

#define M_ 1024
#define N_ 1024
#define D_ 2048

// ================= helpers =================
__device__ __forceinline__ uint32_t smem_to_u32(const void* p) {
    uint32_t a;
    asm("{ .reg .u64 t; cvta.to.shared.u64 t, %1; cvt.u32.u64 %0, t; }" : "=r"(a) : "l"(p));
    return a;
}
#define SMEM_SWIZZLE_128B(b) ((b) ^ (((b) >> 3) & 0x70))

#define LDSM_X4(r, a) \
    asm volatile("ldmatrix.sync.aligned.m8n8.x4.shared.b16 {%0,%1,%2,%3}, [%4];" \
        : "=r"((r)[0]), "=r"((r)[1]), "=r"((r)[2]), "=r"((r)[3]) : "r"(a))
#define LDSM_X4_T(r, a) \
    asm volatile("ldmatrix.sync.aligned.m8n8.x4.trans.shared.b16 {%0,%1,%2,%3}, [%4];" \
        : "=r"((r)[0]), "=r"((r)[1]), "=r"((r)[2]), "=r"((r)[3]) : "r"(a))

__device__ __forceinline__ void mma_f16(float* c, const uint32_t* a, uint32_t b0, uint32_t b1) {
    asm volatile("mma.sync.aligned.m16n8k16.row.col.f32.f16.f16.f32 "
        "{%0,%1,%2,%3}, {%4,%5,%6,%7}, {%8,%9}, {%0,%1,%2,%3};"
        : "+f"(c[0]), "+f"(c[1]), "+f"(c[2]), "+f"(c[3])
        : "r"(a[0]), "r"(a[1]), "r"(a[2]), "r"(a[3]), "r"(b0), "r"(b1));
}

__device__ __forceinline__ float warp_sum(float v) {
    #pragma unroll
    for (int o = 16; o > 0; o >>= 1) v += __shfl_xor_sync(0xffffffffu, v, o);
    return v;
}

// ================= scratch =================
__device__ __half g_vp16[M_ * D_];
__device__ __half g_up16[M_ * D_];
__device__ __half g_uc16[N_ * D_];
__device__ __half g_Sp16[4 * M_ * N_];   // split-K partials (fp16)
__device__ __half g_E16[M_ * N_];        // E = exp(S) (fp16)
__device__ float g_rp[M_], g_rc[N_];
__device__ float g_rinv[M_];             // 1 / rowsum(E)
__device__ float g_psum[8 * N_];         // column partial sums of E (8 strips)
__device__ float g_part[M_];             // FFN term1 per row (u_p . W0)
__device__ float g_ctapart[256];         // FFN partials from dual CTAs

__device__ __forceinline__ void store_h4(__half* dst, size_t off, float4 v) {
    __half2 lo = __halves2half2(__float2half_rn(v.x), __float2half_rn(v.y));
    __half2 hi = __halves2half2(__float2half_rn(v.z), __float2half_rn(v.w));
    *(__half2*)(dst + off)     = lo;
    *(__half2*)(dst + off + 2) = hi;
}

// ================= K0: rp, rc, term1, vp16, up16, uc16 =================
__global__ void rv_kernel(const float* __restrict__ up, const float* __restrict__ uc,
                          const float* __restrict__ wa, const float* __restrict__ W) {
    __shared__ float sm1[8], sm2[8];
    int row = blockIdx.x, t = threadIdx.x;
    int w = t >> 5, l = t & 31;
    if (row < M_) {
        const float* a = up + (size_t)row * D_;
        const float* w1 = wa;
        const float* w3 = wa + 2 * D_;
        const float* W0 = W + (size_t)row * 4 * D_;
        float s = 0.f, s1 = 0.f;
        for (int k = t * 4; k < D_; k += 1024) {
            float4 av = *(const float4*)(a + k);
            float4 w1v = *(const float4*)(w1 + k);
            float4 w3v = *(const float4*)(w3 + k);
            float4 W0v = *(const float4*)(W0 + k);
            s += av.x * w1v.x + av.y * w1v.y + av.z * w1v.z + av.w * w1v.w;
            s1 += av.x * W0v.x + av.y * W0v.y + av.z * W0v.z + av.w * W0v.w;
            store_h4(g_vp16, (size_t)row * D_ + k,
                     make_float4(av.x * w3v.x, av.y * w3v.y, av.z * w3v.z, av.w * w3v.w));
            store_h4(g_up16, (size_t)row * D_ + k, av);
        }
        s = warp_sum(s); s1 = warp_sum(s1);
        if (l == 0) { sm1[w] = s; sm2[w] = s1; }
        __syncthreads();
        if (t == 0) {
            float a0 = 0.f, b0 = 0.f;
            #pragma unroll
            for (int i = 0; i < 8; i++) { a0 += sm1[i]; b0 += sm2[i]; }
            g_rp[row] = a0; g_part[row] = b0;
        }
    } else {
        int r2 = row - M_;
        const float* a = uc + (size_t)r2 * D_;
        const float* w2 = wa + D_;
        float s = 0.f;
        for (int k = t * 4; k < D_; k += 1024) {
            float4 av = *(const float4*)(a + k);
            float4 w2v = *(const float4*)(w2 + k);
            s += av.x * w2v.x + av.y * w2v.y + av.z * w2v.z + av.w * w2v.w;
            store_h4(g_uc16, (size_t)r2 * D_ + k, av);
        }
        s = warp_sum(s);
        if (l == 0) sm1[w] = s;
        __syncthreads();
        if (t == 0) {
            float a0 = 0.f;
            #pragma unroll
            for (int i = 0; i < 8; i++) a0 += sm1[i];
            g_rc[r2] = a0;
        }
    }
}

// ================= merge partials + bias + E=exp(S) + rowsum inverse =================
__global__ void merge_exp() {
    __shared__ float ssm[8];
    int row = blockIdx.x, t = threadIdx.x;
    int w = t >> 5, l = t & 31;
    float rpv = g_rp[row];
    int j = t * 4;
    float4 rc4 = *(const float4*)(g_rc + j);
    float4 o = make_float4(rpv + rc4.x, rpv + rc4.y, rpv + rc4.z, rpv + rc4.w);
    #pragma unroll
    for (int z = 0; z < 4; z++) {
        const __half* P = g_Sp16 + (size_t)z * M_ * N_ + (size_t)row * N_ + j;
        float2 f01 = __half22float2(*(const __half2*)(P));
        float2 f23 = __half22float2(*(const __half2*)(P + 2));
        o.x += f01.x; o.y += f01.y; o.z += f23.x; o.w += f23.y;
    }
    float e0 = __expf(o.x), e1 = __expf(o.y);
    float e2 = __expf(o.z), e3 = __expf(o.w);
    store_h4(g_E16, (size_t)row * N_ + j, make_float4(e0, e1, e2, e3));

    float s = warp_sum(e0 + e1 + e2 + e3);
    if (l == 0) ssm[w] = s;
    __syncthreads();
    if (t == 0) {
        float tot = 0.f;
        #pragma unroll
        for (int i = 0; i < 8; i++) tot += ssm[i];
        g_rinv[row] = 1.0f / tot;
    }
}

// ================= column partial sums of E (vectorized, 8 strips) =================
__global__ void col_sum() {
    // grid (8, 8), block 256: 128 cols x 128 rows per block; uint4 loads (8 cols)
    int t = threadIdx.x;
    int tx = t & 15, ty = t >> 4;          // 16 col-groups x 16 row-threads
    int c = blockIdx.x * 128 + tx * 8;
    int r0 = blockIdx.y * 128;
    float acc[8] = {0.f, 0.f, 0.f, 0.f, 0.f, 0.f, 0.f, 0.f};
    #pragma unroll
    for (int j = 0; j < 8; j++) {
        int r = r0 + ty + j * 16;
        uint4 v = *(const uint4*)(g_E16 + (size_t)r * N_ + c);
        __half2* h = (__half2*)&v;
        #pragma unroll
        for (int q = 0; q < 4; q++) {
            float2 f = __half22float2(h[q]);
            acc[q * 2] += f.x; acc[q * 2 + 1] += f.y;
        }
    }
    __shared__ float sm[16][16][8];
    #pragma unroll
    for (int q = 0; q < 8; q++) sm[ty][tx][q] = acc[q];
    __syncthreads();
    if (t < 128) {
        int cg = t >> 3, q = t & 7;
        float s = 0.f;
        #pragma unroll
        for (int k = 0; k < 16; k++) s += sm[k][cg][q];
        g_psum[blockIdx.y * N_ + blockIdx.x * 128 + cg * 8 + q] = s;
    }
}

// ================= fp16 mma GEMM core: 256x128 tile, warp tile 64x64 =================
#define NSTG 4
#define TILE_A_SZ 32768
#define TILE_B_SZ 16384
#define SMEM_GEMM (NSTG * (TILE_A_SZ + TILE_B_SZ))   // 196608

__device__ __forceinline__ void cp_tileA(uint32_t sdst, const __half* src,
                                         int row0, int ld, int k0, int tid) {
    const char* gb = (const char*)(src + (size_t)row0 * ld + k0);
    size_t rb = (size_t)ld * 2;
    #pragma unroll
    for (int it = 0; it < 8; it++) {
        int idx = tid + it * 256;
        int r = idx >> 3;
        int cb = (idx & 7) << 4;
        const void* g = gb + (size_t)r * rb + cb;
        uint32_t s = sdst + SMEM_SWIZZLE_128B(r * 128 + cb);
        asm volatile("cp.async.cg.shared.global [%0], [%1], 16;" :: "r"(s), "l"(g));
    }
}
// trans A: 64 k-rows x 256 m-cols -> four 64x128B swizzled segments
__device__ __forceinline__ void cp_tileA_trans(uint32_t sdst, const __half* src,
                                               int krow0, int ld, int m0, int tid) {
    const char* gb = (const char*)(src + (size_t)krow0 * ld + m0);
    size_t rb = (size_t)ld * 2;
    #pragma unroll
    for (int it = 0; it < 8; it++) {
        int idx = tid + it * 256;
        int r = idx >> 5;
        int c16 = idx & 31;
        const void* g = gb + (size_t)r * rb + c16 * 16;
        uint32_t off = ((uint32_t)(c16 >> 3) << 13) + ((uint32_t)r << 7) + ((c16 & 7) << 4);
        uint32_t s = sdst + SMEM_SWIZZLE_128B(off);
        asm volatile("cp.async.cg.shared.global [%0], [%1], 16;" :: "r"(s), "l"(g));
    }
}
__device__ __forceinline__ void cp_tileB(uint32_t sdst, const __half* src,
                                         int row0, int ld, int k0, int tid) {
    const char* gb = (const char*)(src + (size_t)row0 * ld + k0);
    size_t rb = (size_t)ld * 2;
    #pragma unroll
    for (int it = 0; it < 4; it++) {
        int idx = tid + it * 256;
        int r = idx >> 3;
        int cb = (idx & 7) << 4;
        const void* g = gb + (size_t)r * rb + cb;
        uint32_t s = sdst + SMEM_SWIZZLE_128B(r * 128 + cb);
        asm volatile("cp.async.cg.shared.global [%0], [%1], 16;" :: "r"(s), "l"(g));
    }
}
// trans B: 64 k-rows x 128 j-cols -> two 64x128B swizzled segments
__device__ __forceinline__ void cp_tileB_trans(uint32_t sdst, const __half* src,
                                               int krow0, int ld, int j0, int tid) {
    const char* gb = (const char*)(src + (size_t)krow0 * ld + j0);
    size_t rb = (size_t)ld * 2;
    #pragma unroll
    for (int it = 0; it < 4; it++) {
        int idx = tid + it * 256;
        int r = idx >> 4;
        int c16 = idx & 15;
        const void* g = gb + (size_t)r * rb + c16 * 16;
        uint32_t off = ((uint32_t)(c16 >> 3) << 13) + ((uint32_t)r << 7) + ((c16 & 7) << 4);
        uint32_t s = sdst + SMEM_SWIZZLE_128B(off);
        asm volatile("cp.async.cg.shared.global [%0], [%1], 16;" :: "r"(s), "l"(g));
    }
}

// warp grid 4x2 (wm=wid>>1, wn=wid&1), warp tile 64x64, acc[4(mt)][8(nt)][4]
template<bool TA, bool TB>
__device__ __forceinline__ void gemm_compute(
    const __half* __restrict__ A, int ldA,
    const __half* __restrict__ B, int ldB,
    int c0, int ncl, int i0, int j0,
    float (&acc)[4][8][4])
{
    extern __shared__ __align__(1024) char smem[];
    uint32_t sb = smem_to_u32(smem);
    const int tid = threadIdx.x;
    const int wid = tid >> 5, lane = tid & 31;
    const int wm = wid >> 1, wn = wid & 1;

    #pragma unroll
    for (int a = 0; a < 4; a++)
        #pragma unroll
        for (int b = 0; b < 8; b++)
            #pragma unroll
            for (int c = 0; c < 4; c++) acc[a][b][c] = 0.f;

    uint32_t cA = 0, cAt[4];
    if (TA) {
        uint32_t q = lane >> 3, rowt = lane & 7;
        uint32_t kr = ((q >> 1) & 1) * 8 + rowt;
        #pragma unroll
        for (int mt = 0; mt < 4; mt++) {
            uint32_t mof = (uint32_t)(wm * 64 + mt * 16) + (q & 1) * 8;
            uint32_t off = ((mof >> 6) << 13) + (kr << 7) + ((mof & 63) << 1);
            cAt[mt] = SMEM_SWIZZLE_128B(off);
        }
    } else {
        cA = (uint32_t)((wm * 64 + (lane & 15)) << 7) + ((lane >> 4) << 4);
        cA ^= ((cA >> 3) & 0x70);
    }
    uint32_t cB;
    if (TB) {
        uint32_t kr = (lane & 7) + (((lane >> 3) & 1) << 3);
        uint32_t jc = ((lane >> 4) & 1) << 3;
        cB = ((uint32_t)wn << 13) + (kr << 7) + (jc << 1);
        cB ^= ((cB >> 3) & 0x70);
    } else {
        uint32_t rowB = (lane & 7) + ((lane >> 4) << 3);
        cB = (uint32_t)((wn * 64 + rowB) << 7) + (((lane >> 3) & 1) << 4);
        cB ^= ((cB >> 3) & 0x70);
    }

    #define STG_A(s) (sb + (s) * (TILE_A_SZ + TILE_B_SZ))
    #define STG_B(s) (sb + (s) * (TILE_A_SZ + TILE_B_SZ) + TILE_A_SZ)
    #define LOAD_CHUNK(st, ci) do { \
        if (TA) cp_tileA_trans(STG_A(st), A, (ci) * 64, ldA, i0, tid); \
        else    cp_tileA(STG_A(st), A, i0, ldA, (ci) * 64, tid); \
        if (TB) cp_tileB_trans(STG_B(st), B, (ci) * 64, ldB, j0, tid); \
        else    cp_tileB(STG_B(st), B, j0, ldB, (ci) * 64, tid); \
    } while (0)

    LOAD_CHUNK(0, c0);
    asm volatile("cp.async.commit_group;" ::: "memory");
    LOAD_CHUNK(1, c0 + 1);
    asm volatile("cp.async.commit_group;" ::: "memory");

    for (int li = 0; li < ncl; li++) {
        int s = li & 3;
        asm volatile("cp.async.wait_group 1;" ::: "memory");
        __syncthreads();
        if (li + 2 < ncl) LOAD_CHUNK((li + 2) & 3, c0 + li + 2);
        asm volatile("cp.async.commit_group;" ::: "memory");

        uint32_t aBase = STG_A(s) + cA;
        uint32_t bBase = STG_B(s) + cB;
        #pragma unroll
        for (int ks = 0; ks < 4; ks++) {
            uint32_t afr[4][4], bfr[4][4];
            #pragma unroll
            for (int mt = 0; mt < 4; mt++) {
                if (TA) LDSM_X4_T(afr[mt], STG_A(s) + cAt[mt] + ks * 2048);
                else    LDSM_X4(afr[mt], (aBase + mt * 2048) ^ (ks << 5));
            }
            #pragma unroll
            for (int p = 0; p < 4; p++) {
                if (TB) LDSM_X4_T(bfr[p], (bBase + ks * 2048) ^ (p << 5));
                else    LDSM_X4(bfr[p], (bBase + p * 2048) ^ (ks << 5));
            }
            #pragma unroll
            for (int mt = 0; mt < 4; mt++) {
                #pragma unroll
                for (int p = 0; p < 4; p++) {
                    mma_f16(acc[mt][p * 2 + 0], afr[mt], bfr[p][0], bfr[p][1]);
                    mma_f16(acc[mt][p * 2 + 1], afr[mt], bfr[p][2], bfr[p][3]);
                }
            }
        }
    }
    #undef STG_A
    #undef STG_B
    #undef LOAD_CHUNK
}

// GEMM1: S partials = vp16 @ uc16^T, split-K x4, fp16 partial output
__global__ __launch_bounds__(256, 1) void gemm_splitk(
    const __half* __restrict__ A, const __half* __restrict__ B, __half* __restrict__ Cp)
{
    int z = blockIdx.z;
    const int q = (D_ / 64) / 4;
    int i0 = blockIdx.y * 256, j0 = blockIdx.x * 128;
    float acc[4][8][4];
    gemm_compute<false, false>(A, D_, B, D_, z * q, q, i0, j0, acc);

    const int lane = threadIdx.x & 31, wid = threadIdx.x >> 5;
    const int wm = wid >> 1, wn = wid & 1;
    const int gid = lane >> 2, tig = lane & 3;
    __half* C = Cp + (size_t)z * M_ * N_;
    #pragma unroll
    for (int mt = 0; mt < 4; mt++) {
        int gi = i0 + wm * 64 + mt * 16 + gid;
        #pragma unroll
        for (int nt = 0; nt < 8; nt++) {
            int gj = j0 + wn * 64 + nt * 8 + tig * 2;
            *(__half2*)(C + (size_t)gi * N_ + gj) =
                __floats2half2_rn(acc[mt][nt][0], acc[mt][nt][1]);
            *(__half2*)(C + (size_t)(gi + 8) * N_ + gj) =
                __floats2half2_rn(acc[mt][nt][2], acc[mt][nt][3]);
        }
    }
}

// GEMM2+3 fused with FFN epilogue, split-K x2.
// z = 2*g + kh: g picks GEMM (0: E@uc, 1: E^T@up), kh picks K half.
__global__ __launch_bounds__(256, 1) void gemm_dual_ffn(
    const __half* __restrict__ E,
    const __half* __restrict__ uc16, const __half* __restrict__ up16,
    const float* __restrict__ up, const float* __restrict__ uc,
    const float* __restrict__ W)
{
    __shared__ float red[8];
    __shared__ float scale[256];
    int g = blockIdx.z >> 1, kh = blockIdx.z & 1;
    int i0 = blockIdx.y * 256, j0 = blockIdx.x * 128;
    int c0 = kh * 8;                       // 8 chunks per K half (K=1024)
    float acc[4][8][4];
    if (g == 0)
        gemm_compute<false, true>(E, N_, uc16, D_, c0, 8, i0, j0, acc);
    else
        gemm_compute<true, true>(E, N_, up16, D_, c0, 8, i0, j0, acc);

    // per-row normalization scale
    {
        int i = threadIdx.x;
        if (g == 0) {
            scale[i] = g_rinv[i0 + i];
        } else {
            float s = 0.f;
            #pragma unroll
            for (int k = 0; k < 8; k++) s += g_psum[k * N_ + i0 + i];
            scale[i] = 1.0f / s;
        }
    }
    __syncthreads();

    const int lane = threadIdx.x & 31, wid = threadIdx.x >> 5;
    const int wm = wid >> 1, wn = wid & 1;
    const int gid = lane >> 2, tig = lane & 3;
    const float* uin = g ? uc : up;
    float part = 0.f;
    #pragma unroll
    for (int mt = 0; mt < 4; mt++) {
        int li0 = wm * 64 + mt * 16 + gid;
        #pragma unroll
        for (int r = 0; r < 2; r++) {
            int gi = i0 + li0 + r * 8;
            float sc = scale[li0 + r * 8];
            const float* Wr = W + (size_t)gi * 4 * D_;
            float rpart = 0.f;
            #pragma unroll
            for (int nt = 0; nt < 8; nt++) {
                int gj = j0 + wn * 64 + nt * 8 + tig * 2;
                float a0 = acc[mt][nt][r * 2 + 0];
                float a1 = acc[mt][nt][r * 2 + 1];
                float2 uv = *(const float2*)(uin + (size_t)gi * D_ + gj);
                if (g == 0) {
                    float2 w1 = *(const float2*)(Wr + D_ + gj);
                    float2 w2 = *(const float2*)(Wr + 2 * D_ + gj);
                    rpart += a0 * (w1.x + uv.x * w2.x) + a1 * (w1.y + uv.y * w2.y);
                } else {
                    float2 w3 = *(const float2*)(Wr + 3 * D_ + gj);
                    rpart += a0 * uv.x * w3.x + a1 * uv.y * w3.y;
                }
            }
            part += sc * rpart;
        }
    }
    part = warp_sum(part);
    if (lane == 0) red[wid] = part;
    __syncthreads();
    if (threadIdx.x == 0) {
        float tot = 0.f;
        #pragma unroll
        for (int i = 0; i < 8; i++) tot += red[i];
        g_ctapart[(size_t)blockIdx.z * 64 + blockIdx.y * 16 + blockIdx.x] = tot;
    }
}

// ================= final scalar =================
__global__ void ffn_final(const float* __restrict__ b, float* __restrict__ out) {
    __shared__ float red[8];
    int t = threadIdx.x;
    float s = 0.f;
    for (int i = t; i < M_; i += 256) s += g_part[i];
    s += g_ctapart[t];
    s = warp_sum(s);
    if ((t & 31) == 0) red[t >> 5] = s;
    __syncthreads();
    if (t == 0) {
        float tot = 0.f;
        #pragma unroll
        for (int i = 0; i < 8; i++) tot += red[i];
        out[0] = fmaxf(tot + b[0], 0.f);
    }
}

// ================= launch =================
extern "C" void kernel_launch(void* const* d_in, const int* in_sizes, int n_in,
                              void* d_out, int out_size) {
    const float* u_p   = (const float*)d_in[0];
    const float* u_c   = (const float*)d_in[1];
    const float* w_a   = (const float*)d_in[2];
    const float* ffn_w = (const float*)d_in[3];
    const float* ffn_b = (const float*)d_in[4];
    float* out = (float*)d_out;

    cudaFuncSetAttribute(gemm_splitk,   cudaFuncAttributeMaxDynamicSharedMemorySize, SMEM_GEMM);
    cudaFuncSetAttribute(gemm_dual_ffn, cudaFuncAttributeMaxDynamicSharedMemorySize, SMEM_GEMM);

    __half *vp16, *up16, *uc16, *E16, *Sp16;
    cudaGetSymbolAddress((void**)&vp16, g_vp16);
    cudaGetSymbolAddress((void**)&up16, g_up16);
    cudaGetSymbolAddress((void**)&uc16, g_uc16);
    cudaGetSymbolAddress((void**)&E16, g_E16);
    cudaGetSymbolAddress((void**)&Sp16, g_Sp16);

    // K0: rp, rc, FFN term1, vp16, up16, uc16
    rv_kernel<<<M_ + N_, 256>>>(u_p, u_c, w_a, ffn_w);

    // GEMM1: fp16 S partials (split-K x4), then merge + E=exp(S) + rowsum
    gemm_splitk<<<dim3(N_ / 128, M_ / 256, 4), 256, SMEM_GEMM>>>(vp16, uc16, Sp16);
    merge_exp<<<M_, 256>>>();

    // column partial sums of E (vectorized)
    col_sum<<<dim3(8, 8), 256>>>();

    // GEMM2 + GEMM3 + FFN fused, split-K x2 (256 CTAs)
    gemm_dual_ffn<<<dim3(D_ / 128, M_ / 256, 4), 256, SMEM_GEMM>>>(
        E16, uc16, up16, u_p, u_c, ffn_w);

    // final scalar
    ffn_final<<<1, 256>>>(ffn_b, out);
}

// round 17
// speedup vs baseline: 1.1062x; 1.1062x over previous
#include <cuda_runtime.h>
#include <cuda_fp16.h>
#include <cstdint>
#include <math.h>

#define M_ 1024
#define N_ 1024
#define D_ 2048

// ================= helpers =================
__device__ __forceinline__ uint32_t smem_to_u32(const void* p) {
    uint32_t a;
    asm("{ .reg .u64 t; cvta.to.shared.u64 t, %1; cvt.u32.u64 %0, t; }" : "=r"(a) : "l"(p));
    return a;
}
#define SMEM_SWIZZLE_128B(b) ((b) ^ (((b) >> 3) & 0x70))

#define LDSM_X4(r, a) \
    asm volatile("ldmatrix.sync.aligned.m8n8.x4.shared.b16 {%0,%1,%2,%3}, [%4];" \
        : "=r"((r)[0]), "=r"((r)[1]), "=r"((r)[2]), "=r"((r)[3]) : "r"(a))
#define LDSM_X4_T(r, a) \
    asm volatile("ldmatrix.sync.aligned.m8n8.x4.trans.shared.b16 {%0,%1,%2,%3}, [%4];" \
        : "=r"((r)[0]), "=r"((r)[1]), "=r"((r)[2]), "=r"((r)[3]) : "r"(a))

__device__ __forceinline__ void mma_f16(float* c, const uint32_t* a, uint32_t b0, uint32_t b1) {
    asm volatile("mma.sync.aligned.m16n8k16.row.col.f32.f16.f16.f32 "
        "{%0,%1,%2,%3}, {%4,%5,%6,%7}, {%8,%9}, {%0,%1,%2,%3};"
        : "+f"(c[0]), "+f"(c[1]), "+f"(c[2]), "+f"(c[3])
        : "r"(a[0]), "r"(a[1]), "r"(a[2]), "r"(a[3]), "r"(b0), "r"(b1));
}

__device__ __forceinline__ float warp_sum(float v) {
    #pragma unroll
    for (int o = 16; o > 0; o >>= 1) v += __shfl_xor_sync(0xffffffffu, v, o);
    return v;
}

// ================= scratch =================
__device__ __half g_vp16[M_ * D_];
__device__ __half g_up16[M_ * D_];
__device__ __half g_uc16[N_ * D_];
__device__ __half g_Sp16[4 * M_ * N_];   // split-K partials (fp16)
__device__ __half g_E16[M_ * N_];        // E = exp(S) (fp16)
__device__ float g_rp[M_], g_rc[N_];
__device__ float g_rinv[M_];             // 1 / rowsum(E)
__device__ float g_psum[32 * N_];        // column partial sums of E (32 strips)
__device__ float g_part[M_];             // FFN term1 per row (u_p . W0)
__device__ float g_ctapart[128];         // FFN partials from dual CTAs

__device__ __forceinline__ void store_h4(__half* dst, size_t off, float4 v) {
    __half2 lo = __halves2half2(__float2half_rn(v.x), __float2half_rn(v.y));
    __half2 hi = __halves2half2(__float2half_rn(v.z), __float2half_rn(v.w));
    *(__half2*)(dst + off)     = lo;
    *(__half2*)(dst + off + 2) = hi;
}

// ================= K0: rp, rc, term1, vp16, up16, uc16 =================
__global__ void rv_kernel(const float* __restrict__ up, const float* __restrict__ uc,
                          const float* __restrict__ wa, const float* __restrict__ W) {
    __shared__ float sm1[8], sm2[8];
    int row = blockIdx.x, t = threadIdx.x;
    int w = t >> 5, l = t & 31;
    if (row < M_) {
        const float* a = up + (size_t)row * D_;
        const float* w1 = wa;
        const float* w3 = wa + 2 * D_;
        const float* W0 = W + (size_t)row * 4 * D_;
        float s = 0.f, s1 = 0.f;
        for (int k = t * 4; k < D_; k += 1024) {
            float4 av = *(const float4*)(a + k);
            float4 w1v = *(const float4*)(w1 + k);
            float4 w3v = *(const float4*)(w3 + k);
            float4 W0v = *(const float4*)(W0 + k);
            s += av.x * w1v.x + av.y * w1v.y + av.z * w1v.z + av.w * w1v.w;
            s1 += av.x * W0v.x + av.y * W0v.y + av.z * W0v.z + av.w * W0v.w;
            store_h4(g_vp16, (size_t)row * D_ + k,
                     make_float4(av.x * w3v.x, av.y * w3v.y, av.z * w3v.z, av.w * w3v.w));
            store_h4(g_up16, (size_t)row * D_ + k, av);
        }
        s = warp_sum(s); s1 = warp_sum(s1);
        if (l == 0) { sm1[w] = s; sm2[w] = s1; }
        __syncthreads();
        if (t == 0) {
            float a0 = 0.f, b0 = 0.f;
            #pragma unroll
            for (int i = 0; i < 8; i++) { a0 += sm1[i]; b0 += sm2[i]; }
            g_rp[row] = a0; g_part[row] = b0;
        }
    } else {
        int r2 = row - M_;
        const float* a = uc + (size_t)r2 * D_;
        const float* w2 = wa + D_;
        float s = 0.f;
        for (int k = t * 4; k < D_; k += 1024) {
            float4 av = *(const float4*)(a + k);
            float4 w2v = *(const float4*)(w2 + k);
            s += av.x * w2v.x + av.y * w2v.y + av.z * w2v.z + av.w * w2v.w;
            store_h4(g_uc16, (size_t)r2 * D_ + k, av);
        }
        s = warp_sum(s);
        if (l == 0) sm1[w] = s;
        __syncthreads();
        if (t == 0) {
            float a0 = 0.f;
            #pragma unroll
            for (int i = 0; i < 8; i++) a0 += sm1[i];
            g_rc[r2] = a0;
        }
    }
}

// ================= merge partials + bias + E=exp(S) + rowsum inverse =================
__global__ void merge_exp() {
    __shared__ float ssm[8];
    int row = blockIdx.x, t = threadIdx.x;
    int w = t >> 5, l = t & 31;
    float rpv = g_rp[row];
    int j = t * 4;
    float4 rc4 = *(const float4*)(g_rc + j);
    float4 o = make_float4(rpv + rc4.x, rpv + rc4.y, rpv + rc4.z, rpv + rc4.w);
    #pragma unroll
    for (int z = 0; z < 4; z++) {
        const __half* P = g_Sp16 + (size_t)z * M_ * N_ + (size_t)row * N_ + j;
        float2 f01 = __half22float2(*(const __half2*)(P));
        float2 f23 = __half22float2(*(const __half2*)(P + 2));
        o.x += f01.x; o.y += f01.y; o.z += f23.x; o.w += f23.y;
    }
    float e0 = __expf(o.x), e1 = __expf(o.y);
    float e2 = __expf(o.z), e3 = __expf(o.w);
    store_h4(g_E16, (size_t)row * N_ + j, make_float4(e0, e1, e2, e3));

    float s = warp_sum(e0 + e1 + e2 + e3);
    if (l == 0) ssm[w] = s;
    __syncthreads();
    if (t == 0) {
        float tot = 0.f;
        #pragma unroll
        for (int i = 0; i < 8; i++) tot += ssm[i];
        g_rinv[row] = 1.0f / tot;
    }
}

// ================= column partial sums of E (32 strips of 32 rows) =================
__global__ void col_sum() {
    int tx = threadIdx.x, ty = threadIdx.y;
    int c = blockIdx.x * 128 + tx;
    int r0 = blockIdx.y * 32;
    float s0 = 0.f, s1 = 0.f;
    #pragma unroll
    for (int jj = 0; jj < 8; jj += 2) {
        s0 += __half2float(g_E16[(size_t)(r0 + ty + jj * 4) * N_ + c]);
        s1 += __half2float(g_E16[(size_t)(r0 + ty + (jj + 1) * 4) * N_ + c]);
    }
    __shared__ float sm[4][128];
    sm[ty][tx] = s0 + s1;
    __syncthreads();
    if (ty == 0)
        g_psum[blockIdx.y * N_ + c] = sm[0][tx] + sm[1][tx] + sm[2][tx] + sm[3][tx];
}

// ================= fp16 mma GEMM core: 256x128 tile, warp tile 64x64 =================
#define NSTG 4
#define TILE_A_SZ 32768
#define TILE_B_SZ 16384
#define SMEM_GEMM (NSTG * (TILE_A_SZ + TILE_B_SZ))   // 196608

__device__ __forceinline__ void cp_tileA(uint32_t sdst, const __half* src,
                                         int row0, int ld, int k0, int tid) {
    const char* gb = (const char*)(src + (size_t)row0 * ld + k0);
    size_t rb = (size_t)ld * 2;
    #pragma unroll
    for (int it = 0; it < 8; it++) {
        int idx = tid + it * 256;
        int r = idx >> 3;
        int cb = (idx & 7) << 4;
        const void* g = gb + (size_t)r * rb + cb;
        uint32_t s = sdst + SMEM_SWIZZLE_128B(r * 128 + cb);
        asm volatile("cp.async.cg.shared.global [%0], [%1], 16;" :: "r"(s), "l"(g));
    }
}
// trans A: 64 k-rows x 256 m-cols -> four 64x128B swizzled segments
__device__ __forceinline__ void cp_tileA_trans(uint32_t sdst, const __half* src,
                                               int krow0, int ld, int m0, int tid) {
    const char* gb = (const char*)(src + (size_t)krow0 * ld + m0);
    size_t rb = (size_t)ld * 2;
    #pragma unroll
    for (int it = 0; it < 8; it++) {
        int idx = tid + it * 256;
        int r = idx >> 5;
        int c16 = idx & 31;
        const void* g = gb + (size_t)r * rb + c16 * 16;
        uint32_t off = ((uint32_t)(c16 >> 3) << 13) + ((uint32_t)r << 7) + ((c16 & 7) << 4);
        uint32_t s = sdst + SMEM_SWIZZLE_128B(off);
        asm volatile("cp.async.cg.shared.global [%0], [%1], 16;" :: "r"(s), "l"(g));
    }
}
__device__ __forceinline__ void cp_tileB(uint32_t sdst, const __half* src,
                                         int row0, int ld, int k0, int tid) {
    const char* gb = (const char*)(src + (size_t)row0 * ld + k0);
    size_t rb = (size_t)ld * 2;
    #pragma unroll
    for (int it = 0; it < 4; it++) {
        int idx = tid + it * 256;
        int r = idx >> 3;
        int cb = (idx & 7) << 4;
        const void* g = gb + (size_t)r * rb + cb;
        uint32_t s = sdst + SMEM_SWIZZLE_128B(r * 128 + cb);
        asm volatile("cp.async.cg.shared.global [%0], [%1], 16;" :: "r"(s), "l"(g));
    }
}
// trans B: 64 k-rows x 128 j-cols -> two 64x128B swizzled segments
__device__ __forceinline__ void cp_tileB_trans(uint32_t sdst, const __half* src,
                                               int krow0, int ld, int j0, int tid) {
    const char* gb = (const char*)(src + (size_t)krow0 * ld + j0);
    size_t rb = (size_t)ld * 2;
    #pragma unroll
    for (int it = 0; it < 4; it++) {
        int idx = tid + it * 256;
        int r = idx >> 4;
        int c16 = idx & 15;
        const void* g = gb + (size_t)r * rb + c16 * 16;
        uint32_t off = ((uint32_t)(c16 >> 3) << 13) + ((uint32_t)r << 7) + ((c16 & 7) << 4);
        uint32_t s = sdst + SMEM_SWIZZLE_128B(off);
        asm volatile("cp.async.cg.shared.global [%0], [%1], 16;" :: "r"(s), "l"(g));
    }
}

// warp grid 4x2 (wm=wid>>1, wn=wid&1), warp tile 64x64, acc[4(mt)][8(nt)][4]
template<bool TA, bool TB>
__device__ __forceinline__ void gemm_compute(
    const __half* __restrict__ A, int ldA,
    const __half* __restrict__ B, int ldB,
    int c0, int ncl, int i0, int j0,
    float (&acc)[4][8][4])
{
    extern __shared__ __align__(1024) char smem[];
    uint32_t sb = smem_to_u32(smem);
    const int tid = threadIdx.x;
    const int wid = tid >> 5, lane = tid & 31;
    const int wm = wid >> 1, wn = wid & 1;

    #pragma unroll
    for (int a = 0; a < 4; a++)
        #pragma unroll
        for (int b = 0; b < 8; b++)
            #pragma unroll
            for (int c = 0; c < 4; c++) acc[a][b][c] = 0.f;

    uint32_t cA = 0, cAt[4];
    if (TA) {
        uint32_t q = lane >> 3, rowt = lane & 7;
        uint32_t kr = ((q >> 1) & 1) * 8 + rowt;
        #pragma unroll
        for (int mt = 0; mt < 4; mt++) {
            uint32_t mof = (uint32_t)(wm * 64 + mt * 16) + (q & 1) * 8;
            uint32_t off = ((mof >> 6) << 13) + (kr << 7) + ((mof & 63) << 1);
            cAt[mt] = SMEM_SWIZZLE_128B(off);
        }
    } else {
        cA = (uint32_t)((wm * 64 + (lane & 15)) << 7) + ((lane >> 4) << 4);
        cA ^= ((cA >> 3) & 0x70);
    }
    uint32_t cB;
    if (TB) {
        uint32_t kr = (lane & 7) + (((lane >> 3) & 1) << 3);
        uint32_t jc = ((lane >> 4) & 1) << 3;
        cB = ((uint32_t)wn << 13) + (kr << 7) + (jc << 1);
        cB ^= ((cB >> 3) & 0x70);
    } else {
        uint32_t rowB = (lane & 7) + ((lane >> 4) << 3);
        cB = (uint32_t)((wn * 64 + rowB) << 7) + (((lane >> 3) & 1) << 4);
        cB ^= ((cB >> 3) & 0x70);
    }

    #define STG_A(s) (sb + (s) * (TILE_A_SZ + TILE_B_SZ))
    #define STG_B(s) (sb + (s) * (TILE_A_SZ + TILE_B_SZ) + TILE_A_SZ)
    #define LOAD_CHUNK(st, ci) do { \
        if (TA) cp_tileA_trans(STG_A(st), A, (ci) * 64, ldA, i0, tid); \
        else    cp_tileA(STG_A(st), A, i0, ldA, (ci) * 64, tid); \
        if (TB) cp_tileB_trans(STG_B(st), B, (ci) * 64, ldB, j0, tid); \
        else    cp_tileB(STG_B(st), B, j0, ldB, (ci) * 64, tid); \
    } while (0)

    LOAD_CHUNK(0, c0);
    asm volatile("cp.async.commit_group;" ::: "memory");
    LOAD_CHUNK(1, c0 + 1);
    asm volatile("cp.async.commit_group;" ::: "memory");

    for (int li = 0; li < ncl; li++) {
        int s = li & 3;
        asm volatile("cp.async.wait_group 1;" ::: "memory");
        __syncthreads();
        if (li + 2 < ncl) LOAD_CHUNK((li + 2) & 3, c0 + li + 2);
        asm volatile("cp.async.commit_group;" ::: "memory");

        uint32_t aBase = STG_A(s) + cA;
        uint32_t bBase = STG_B(s) + cB;
        #pragma unroll
        for (int ks = 0; ks < 4; ks++) {
            uint32_t afr[4][4], bfr[4][4];
            #pragma unroll
            for (int mt = 0; mt < 4; mt++) {
                if (TA) LDSM_X4_T(afr[mt], STG_A(s) + cAt[mt] + ks * 2048);
                else    LDSM_X4(afr[mt], (aBase + mt * 2048) ^ (ks << 5));
            }
            #pragma unroll
            for (int p = 0; p < 4; p++) {
                if (TB) LDSM_X4_T(bfr[p], (bBase + ks * 2048) ^ (p << 5));
                else    LDSM_X4(bfr[p], (bBase + p * 2048) ^ (ks << 5));
            }
            #pragma unroll
            for (int mt = 0; mt < 4; mt++) {
                #pragma unroll
                for (int p = 0; p < 4; p++) {
                    mma_f16(acc[mt][p * 2 + 0], afr[mt], bfr[p][0], bfr[p][1]);
                    mma_f16(acc[mt][p * 2 + 1], afr[mt], bfr[p][2], bfr[p][3]);
                }
            }
        }
    }
    #undef STG_A
    #undef STG_B
    #undef LOAD_CHUNK
}

// GEMM1: S partials = vp16 @ uc16^T, split-K x4, fp16 partial output
__global__ __launch_bounds__(256, 1) void gemm_splitk(
    const __half* __restrict__ A, const __half* __restrict__ B, __half* __restrict__ Cp)
{
    int z = blockIdx.z;
    const int q = (D_ / 64) / 4;
    int i0 = blockIdx.y * 256, j0 = blockIdx.x * 128;
    float acc[4][8][4];
    gemm_compute<false, false>(A, D_, B, D_, z * q, q, i0, j0, acc);

    const int lane = threadIdx.x & 31, wid = threadIdx.x >> 5;
    const int wm = wid >> 1, wn = wid & 1;
    const int gid = lane >> 2, tig = lane & 3;
    __half* C = Cp + (size_t)z * M_ * N_;
    #pragma unroll
    for (int mt = 0; mt < 4; mt++) {
        int gi = i0 + wm * 64 + mt * 16 + gid;
        #pragma unroll
        for (int nt = 0; nt < 8; nt++) {
            int gj = j0 + wn * 64 + nt * 8 + tig * 2;
            *(__half2*)(C + (size_t)gi * N_ + gj) =
                __floats2half2_rn(acc[mt][nt][0], acc[mt][nt][1]);
            *(__half2*)(C + (size_t)(gi + 8) * N_ + gj) =
                __floats2half2_rn(acc[mt][nt][2], acc[mt][nt][3]);
        }
    }
}

// GEMM2+3 fused with FFN epilogue. A = E (z=0, non-trans) or E^T (z=1, trans-A).
// Softmax normalization applied as per-row scalar in the epilogue.
__global__ __launch_bounds__(256, 1) void gemm_dual_ffn(
    const __half* __restrict__ E,
    const __half* __restrict__ uc16, const __half* __restrict__ up16,
    const float* __restrict__ up, const float* __restrict__ uc,
    const float* __restrict__ W)
{
    __shared__ float red[8];
    __shared__ float scale[256];
    int z = blockIdx.z;
    int i0 = blockIdx.y * 256, j0 = blockIdx.x * 128;
    float acc[4][8][4];
    if (z == 0)
        gemm_compute<false, true>(E, N_, uc16, D_, 0, N_ / 64, i0, j0, acc);
    else
        gemm_compute<true, true>(E, N_, up16, D_, 0, M_ / 64, i0, j0, acc);

    // per-row normalization scale
    {
        int i = threadIdx.x;
        if (z == 0) {
            scale[i] = g_rinv[i0 + i];
        } else {
            float s = 0.f;
            #pragma unroll
            for (int k = 0; k < 32; k++) s += g_psum[k * N_ + i0 + i];
            scale[i] = 1.0f / s;
        }
    }
    __syncthreads();

    const int lane = threadIdx.x & 31, wid = threadIdx.x >> 5;
    const int wm = wid >> 1, wn = wid & 1;
    const int gid = lane >> 2, tig = lane & 3;
    const float* uin = z ? uc : up;
    float part = 0.f;
    #pragma unroll
    for (int mt = 0; mt < 4; mt++) {
        int li0 = wm * 64 + mt * 16 + gid;
        #pragma unroll
        for (int r = 0; r < 2; r++) {
            int gi = i0 + li0 + r * 8;
            float sc = scale[li0 + r * 8];
            const float* Wr = W + (size_t)gi * 4 * D_;
            float rpart = 0.f;
            #pragma unroll
            for (int nt = 0; nt < 8; nt++) {
                int gj = j0 + wn * 64 + nt * 8 + tig * 2;
                float a0 = acc[mt][nt][r * 2 + 0];
                float a1 = acc[mt][nt][r * 2 + 1];
                float2 uv = *(const float2*)(uin + (size_t)gi * D_ + gj);
                if (z == 0) {
                    float2 w1 = *(const float2*)(Wr + D_ + gj);
                    float2 w2 = *(const float2*)(Wr + 2 * D_ + gj);
                    rpart += a0 * (w1.x + uv.x * w2.x) + a1 * (w1.y + uv.y * w2.y);
                } else {
                    float2 w3 = *(const float2*)(Wr + 3 * D_ + gj);
                    rpart += a0 * uv.x * w3.x + a1 * uv.y * w3.y;
                }
            }
            part += sc * rpart;
        }
    }
    part = warp_sum(part);
    if (lane == 0) red[wid] = part;
    __syncthreads();
    if (threadIdx.x == 0) {
        float tot = 0.f;
        #pragma unroll
        for (int i = 0; i < 8; i++) tot += red[i];
        g_ctapart[z * 64 + blockIdx.y * 16 + blockIdx.x] = tot;
    }
}

// ================= final scalar =================
__global__ void ffn_final(const float* __restrict__ b, float* __restrict__ out) {
    __shared__ float red[8];
    int t = threadIdx.x;
    float s = 0.f;
    for (int i = t; i < M_; i += 256) s += g_part[i];
    if (t < 128) s += g_ctapart[t];
    s = warp_sum(s);
    if ((t & 31) == 0) red[t >> 5] = s;
    __syncthreads();
    if (t == 0) {
        float tot = 0.f;
        #pragma unroll
        for (int i = 0; i < 8; i++) tot += red[i];
        out[0] = fmaxf(tot + b[0], 0.f);
    }
}

// ================= launch =================
extern "C" void kernel_launch(void* const* d_in, const int* in_sizes, int n_in,
                              void* d_out, int out_size) {
    const float* u_p   = (const float*)d_in[0];
    const float* u_c   = (const float*)d_in[1];
    const float* w_a   = (const float*)d_in[2];
    const float* ffn_w = (const float*)d_in[3];
    const float* ffn_b = (const float*)d_in[4];
    float* out = (float*)d_out;

    cudaFuncSetAttribute(gemm_splitk,   cudaFuncAttributeMaxDynamicSharedMemorySize, SMEM_GEMM);
    cudaFuncSetAttribute(gemm_dual_ffn, cudaFuncAttributeMaxDynamicSharedMemorySize, SMEM_GEMM);

    __half *vp16, *up16, *uc16, *E16, *Sp16;
    cudaGetSymbolAddress((void**)&vp16, g_vp16);
    cudaGetSymbolAddress((void**)&up16, g_up16);
    cudaGetSymbolAddress((void**)&uc16, g_uc16);
    cudaGetSymbolAddress((void**)&E16, g_E16);
    cudaGetSymbolAddress((void**)&Sp16, g_Sp16);

    // K0: rp, rc, FFN term1, vp16, up16, uc16
    rv_kernel<<<M_ + N_, 256>>>(u_p, u_c, w_a, ffn_w);

    // GEMM1: fp16 S partials (split-K x4), then merge + E=exp(S) + rowsum
    gemm_splitk<<<dim3(N_ / 128, M_ / 256, 4), 256, SMEM_GEMM>>>(vp16, uc16, Sp16);
    merge_exp<<<M_, 256>>>();

    // column partial sums of E (combined in dual epilogue)
    col_sum<<<dim3(N_ / 128, 32), dim3(128, 4)>>>();

    // GEMM2 + GEMM3 + FFN fused (A = E / E^T, normalization in epilogue)
    gemm_dual_ffn<<<dim3(D_ / 128, M_ / 256, 2), 256, SMEM_GEMM>>>(
        E16, uc16, up16, u_p, u_c, ffn_w);

    // final scalar
    ffn_final<<<1, 256>>>(ffn_b, out);
}